// round 9
// baseline (speedup 1.0000x reference)
#include <cuda_runtime.h>
#include <cstdint>

#define D_A      1024
#define NEXP     64
#define BATCH    256
#define POOL_DIM 33792
#define U_END    16384
#define V_END    32768
#define KEXT     1088
#define LN_EPS   1e-5f

#define NK1 32            /* 1024/32 */
#define NK2 34            /* 1088/32 */
#define A_STG1 4096       /* 32 rows x 128B */
#define B_STG1 8192       /* 64 rows x 128B */
#define A_STG2 4096       /* 32 rows x 128B */
#define B_STG2 4096       /* 32 rows x 128B */
#define EP1 68            /* k1 epi stride floats */
#define EP2 36            /* k2 epi stride floats */

// ---------------- scratch ----------------
__device__ __align__(128) float  g_BmatT[(size_t)1024 * KEXT];  // [c][k]
__device__ __align__(128) float  g_S[BATCH * KEXT];             // [b][k]
__device__ __align__(128) float  g_P[BATCH * 1024];
__device__ __align__(128) float  g_X[BATCH * 1024];
__device__ __align__(128) float2 g_part[BATCH * 32];            // [row][bn]

// ---------------- helpers ----------------
__device__ __forceinline__ uint32_t smem_u32(const void* p) {
    uint32_t a;
    asm("{ .reg .u64 t; cvta.to.shared.u64 t, %1; cvt.u32.u64 %0, t; }" : "=r"(a) : "l"(p));
    return a;
}
__device__ __forceinline__ uint32_t swz(uint32_t off) { return off ^ ((off >> 3) & 0x70); }
__device__ __forceinline__ void cpa16(uint32_t saddr, const void* g) {
    asm volatile("cp.async.cg.shared.global [%0], [%1], 16;\n" :: "r"(saddr), "l"(g));
}
__device__ __forceinline__ void cp_commit() { asm volatile("cp.async.commit_group;\n"); }
template<int N> __device__ __forceinline__ void cp_wait() {
    asm volatile("cp.async.wait_group %0;\n" :: "n"(N));
}
#define LDSM4(R, addr) \
    asm volatile("ldmatrix.sync.aligned.m8n8.x4.shared.b16 {%0,%1,%2,%3}, [%4];" \
        : "=r"((R)[0]), "=r"((R)[1]), "=r"((R)[2]), "=r"((R)[3]) : "r"(addr))
__device__ __forceinline__ void mma_tf32(float* c, const uint32_t* a, const uint32_t* b) {
    asm volatile(
        "mma.sync.aligned.m16n8k8.row.col.f32.tf32.tf32.f32 "
        "{%0,%1,%2,%3}, {%4,%5,%6,%7}, {%8,%9}, {%0,%1,%2,%3};\n"
        : "+f"(c[0]), "+f"(c[1]), "+f"(c[2]), "+f"(c[3])
        : "r"(a[0]), "r"(a[1]), "r"(a[2]), "r"(a[3]), "r"(b[0]), "r"(b[1]));
}

// ---------------- prep role (17 blocks x 256 threads) -----------------------
__device__ void prep_role(int pid, float* sf, const float* __restrict__ pool,
                          const float* __restrict__ alpha) {
    const int tid = threadIdx.x;
    if (pid == 16) {
        #pragma unroll 8
        for (int it = 0; it < 64; it++) {
            int e = tid + it * 256;
            int b = e >> 6, n = e & 63;
            g_S[(size_t)b * KEXT + 1024 + n] = alpha[b * NEXP + n];
        }
        return;
    }
    for (int half = 0; half < 2; half++) {
        const int c0 = pid * 64 + half * 32;
        for (int ng = 0; ng < 4; ng++) {
            #pragma unroll
            for (int it = 0; it < 8; it++) {
                int e = tid + it * 256;
                int nl = e >> 7, i4 = e & 127;
                const float4* src = (const float4*)(pool + (size_t)(ng * 16 + nl) * POOL_DIM + c0 * 16) + i4;
                *(float4*)(sf + nl * 528 + i4 * 4) = *src;
            }
            __syncthreads();
            #pragma unroll 8
            for (int it = 0; it < 32; it++) {
                int e = tid + it * 256;
                int cl = e >> 8, j = e & 255;
                int nl = j >> 4, r = j & 15;
                g_BmatT[(size_t)(c0 + cl) * KEXT + ng * 256 + j] = sf[nl * 528 + cl * 16 + r];
            }
            __syncthreads();
        }
        #pragma unroll
        for (int it = 0; it < 8; it++) {
            int e = tid + it * 256;
            int n = e >> 5, cl = e & 31;
            sf[n * 33 + cl] = pool[(size_t)n * POOL_DIM + V_END + c0 + cl];
        }
        __syncthreads();
        #pragma unroll
        for (int it = 0; it < 8; it++) {
            int e = tid + it * 256;
            int cl = e >> 6, n = e & 63;
            g_BmatT[(size_t)(c0 + cl) * KEXT + 1024 + n] = sf[n * 33 + cl];
        }
        __syncthreads();
    }
}

// ---------------- k1: blocks 0..16 prep; 17..272 GEMM1 (32x64, 8 warps) -----
// C[256,2048] = h_A * [W_base | V]^T ; cols<1024 -> g_P, cols>=1024 -> g_S*alpha
__global__ void __launch_bounds__(256) k1_kernel(const float* __restrict__ hA,
                                                 const float* __restrict__ W,
                                                 const float* __restrict__ pool,
                                                 const float* __restrict__ alpha) {
    __shared__ __align__(128) float smem_all[12288];   // 49152 B (4 stages x 12KB)
    const int bid = blockIdx.x;
    if (bid < 17) { prep_role(bid, smem_all, pool, alpha); return; }

    const uint32_t sb = smem_u32(smem_all);
    const int gb = bid - 17;
    const int bm = gb >> 5;           // 0..7 (32-row tiles)
    const int bn = gb & 31;           // 0..31 (64-col tiles)
    const int tid = threadIdx.x;
    const int lane = tid & 31, warp = tid >> 5;
    const int wm = warp & 1;          // 2 row groups of 16
    const int wn = warp >> 1;         // 4 col groups of 16
    const int g = lane >> 2, tig = lane & 3;

    const uint32_t sbA = sb;                   // 4 stages x 4096
    const uint32_t sbB = sb + 4 * A_STG1;      // 4 stages x 8192

    // cp.async maps: A 1 chunk/thread, B 2 chunks/thread
    const float* aPtr; uint32_t aDst;
    {
        int row = tid >> 3, c8 = tid & 7;
        aPtr = hA + (size_t)(bm * 32 + row) * D_A + c8 * 4;
        aDst = swz(row * 128 + c8 * 16);
    }
    const float* bPtr[2]; uint32_t bDst[2];
    #pragma unroll
    for (int q = 0; q < 2; q++) {
        int id = tid + q * 256;
        int row = id >> 3, c8 = id & 7;
        int j = bn * 64 + row;
        const float* base = (bn < 16)
            ? (W + (size_t)j * D_A)
            : (pool + (size_t)((j - 1024) >> 4) * POOL_DIM + U_END + (size_t)((j - 1024) & 15) * D_A);
        bPtr[q] = base + c8 * 4;
        bDst[q] = swz(row * 128 + c8 * 16);
    }
    auto fill = [&](int s, int kc) {
        const int off = kc * 32;
        cpa16(sbA + s * A_STG1 + aDst, aPtr + off);
        #pragma unroll
        for (int q = 0; q < 2; q++)
            cpa16(sbB + s * B_STG1 + bDst[q], bPtr[q] + off);
    };

    // ldmatrix addresses: A m16 (1 frag), B n16 (1 frag -> 2 mma B operands)
    uint32_t aBase, aXor, bBase, bXor;
    const uint32_t ahi = ((lane >> 4) & 1) * 16;
    const uint32_t bhi = ((lane >> 3) & 1) * 16;
    {
        int r = wm * 16 + (lane & 7) + ((lane >> 3) & 1) * 8;
        aBase = r * 128; aXor = (r & 7) << 4;
    }
    {
        int r = wn * 16 + (lane & 7) + ((lane >> 4) & 1) * 8;
        bBase = r * 128; bXor = (r & 7) << 4;
    }

    float acc[2][4];
    #pragma unroll
    for (int j = 0; j < 2; j++)
        #pragma unroll
        for (int e = 0; e < 4; e++) acc[j][e] = 0.f;

    fill(0, 0); cp_commit(); fill(1, 1); cp_commit(); fill(2, 2); cp_commit();

    for (int i = 0; i < NK1; i++) {
        cp_wait<2>();
        __syncthreads();
        if (i + 3 < NK1) fill((i + 3) & 3, i + 3);
        cp_commit();
        const int s = i & 3;
        const uint32_t sA = sbA + s * A_STG1;
        const uint32_t sB = sbB + s * B_STG1;
        uint32_t a[2][4], b[2][4];
        LDSM4(a[0], sA + aBase + (ahi ^ aXor));
        LDSM4(b[0], sB + bBase + (bhi ^ bXor));
        #pragma unroll
        for (int kk = 0; kk < 4; kk++) {
            const int cur = kk & 1, nxt = cur ^ 1;
            if (kk < 3) {
                LDSM4(a[nxt], sA + aBase + (((kk + 1) * 32 + ahi) ^ aXor));
                LDSM4(b[nxt], sB + bBase + (((kk + 1) * 32 + bhi) ^ bXor));
            }
            #pragma unroll
            for (int jn = 0; jn < 2; jn++)
                mma_tf32(acc[jn], a[cur], &b[cur][jn * 2]);
        }
    }
    __syncthreads();

    // stage accumulators through smem, then coalesced float4 out
    float* se = smem_all;
    #pragma unroll
    for (int jn = 0; jn < 2; jn++) {
        int r0 = wm * 16 + g;
        int c  = wn * 16 + jn * 8 + 2 * tig;
        se[r0 * EP1 + c]           = acc[jn][0];
        se[r0 * EP1 + c + 1]       = acc[jn][1];
        se[(r0 + 8) * EP1 + c]     = acc[jn][2];
        se[(r0 + 8) * EP1 + c + 1] = acc[jn][3];
    }
    __syncthreads();
    #pragma unroll
    for (int it = 0; it < 2; it++) {
        int id = tid + it * 256;
        int row = id >> 4, c4 = id & 15;
        float4 v = *(const float4*)(se + row * EP1 + c4 * 4);
        int rowg = bm * 32 + row;
        if (bn < 16) {
            ((float4*)g_P)[(size_t)rowg * 256 + bn * 16 + c4] = v;
        } else {
            int n = (bn - 16) * 4 + (c4 >> 2);
            float a = alpha[rowg * NEXP + n];
            v.x *= a; v.y *= a; v.z *= a; v.w *= a;
            ((float4*)g_S)[(size_t)rowg * 272 + (bn - 16) * 16 + c4] = v;
        }
    }
}

// ---------------- k2: GEMM2 32x32, 4 warps, 6 stages -------------------------
// X = hA + gamma*(S@BmatT^T + P + b_base)
__global__ void __launch_bounds__(128) k2_kernel(const float* __restrict__ hA,
                                                 const float* __restrict__ bbase,
                                                 const float* __restrict__ gamma_p) {
    __shared__ __align__(128) float smem_all[12288];   // 49152 B (6 stages x 8KB)
    const uint32_t sb = smem_u32(smem_all);
    const int bid = blockIdx.x;
    const int bm = bid >> 5;          // 0..7 (32-row tiles)
    const int bn = bid & 31;          // 0..31 (32-col tiles)
    const int tid = threadIdx.x;
    const int lane = tid & 31, warp = tid >> 5;
    const int wm = warp & 1;          // 2 row groups of 16
    const int wn = warp >> 1;         // 2 col groups of 16
    const int g = lane >> 2, tig = lane & 3;

    const uint32_t sbA = sb;                   // 6 stages x 4096
    const uint32_t sbB = sb + 6 * A_STG2;      // 6 stages x 4096

    const float* aPtr[2]; uint32_t aDst[2];
    const float* bPtr[2]; uint32_t bDst[2];
    #pragma unroll
    for (int q = 0; q < 2; q++) {
        int id = tid + q * 128;
        int row = id >> 3, c8 = id & 7;
        aPtr[q] = g_S + (size_t)(bm * 32 + row) * KEXT + c8 * 4;
        aDst[q] = swz(row * 128 + c8 * 16);
        bPtr[q] = g_BmatT + (size_t)(bn * 32 + row) * KEXT + c8 * 4;
        bDst[q] = swz(row * 128 + c8 * 16);
    }
    auto fill = [&](int s, int kc) {
        const int off = kc * 32;
        #pragma unroll
        for (int q = 0; q < 2; q++) {
            cpa16(sbA + s * A_STG2 + aDst[q], aPtr[q] + off);
            cpa16(sbB + s * B_STG2 + bDst[q], bPtr[q] + off);
        }
    };

    uint32_t aBase, aXor, bBase, bXor;
    const uint32_t ahi = ((lane >> 4) & 1) * 16;
    const uint32_t bhi = ((lane >> 3) & 1) * 16;
    {
        int r = wm * 16 + (lane & 7) + ((lane >> 3) & 1) * 8;
        aBase = r * 128; aXor = (r & 7) << 4;
    }
    {
        int r = wn * 16 + (lane & 7) + ((lane >> 4) & 1) * 8;
        bBase = r * 128; bXor = (r & 7) << 4;
    }

    float acc[2][4];
    #pragma unroll
    for (int j = 0; j < 2; j++)
        #pragma unroll
        for (int e = 0; e < 4; e++) acc[j][e] = 0.f;

    fill(0, 0); cp_commit(); fill(1, 1); cp_commit(); fill(2, 2); cp_commit();
    fill(3, 3); cp_commit(); fill(4, 4); cp_commit();

    int s = 0, sw = 5;
    for (int i = 0; i < NK2; i++) {
        cp_wait<4>();
        __syncthreads();
        if (i + 5 < NK2) fill(sw, i + 5);
        cp_commit();
        const uint32_t sA = sbA + s * A_STG2;
        const uint32_t sB = sbB + s * B_STG2;
        uint32_t a[2][4], b[2][4];
        LDSM4(a[0], sA + aBase + (ahi ^ aXor));
        LDSM4(b[0], sB + bBase + (bhi ^ bXor));
        #pragma unroll
        for (int kk = 0; kk < 4; kk++) {
            const int cur = kk & 1, nxt = cur ^ 1;
            if (kk < 3) {
                LDSM4(a[nxt], sA + aBase + (((kk + 1) * 32 + ahi) ^ aXor));
                LDSM4(b[nxt], sB + bBase + (((kk + 1) * 32 + bhi) ^ bXor));
            }
            #pragma unroll
            for (int jn = 0; jn < 2; jn++)
                mma_tf32(acc[jn], a[cur], &b[cur][jn * 2]);
        }
        s = (s == 5) ? 0 : s + 1;
        sw = (sw == 5) ? 0 : sw + 1;
    }
    __syncthreads();

    float* se = smem_all;
    #pragma unroll
    for (int jn = 0; jn < 2; jn++) {
        int r0 = wm * 16 + g;
        int c  = wn * 16 + jn * 8 + 2 * tig;
        se[r0 * EP2 + c]           = acc[jn][0];
        se[r0 * EP2 + c + 1]       = acc[jn][1];
        se[(r0 + 8) * EP2 + c]     = acc[jn][2];
        se[(r0 + 8) * EP2 + c + 1] = acc[jn][3];
    }
    __syncthreads();
    const float gam = *gamma_p;
    #pragma unroll
    for (int it = 0; it < 2; it++) {
        int id = tid + it * 128;
        int row = id >> 3, c4 = id & 7;
        float4 v = *(const float4*)(se + row * EP2 + c4 * 4);
        int rowg = bm * 32 + row;
        int cc4 = bn * 8 + c4;
        float4 p4 = ((const float4*)g_P)[(size_t)rowg * 256 + cc4];
        float4 b4 = ((const float4*)bbase)[cc4];
        float4 h4 = ((const float4*)hA)[(size_t)rowg * 256 + cc4];
        float4 x;
        x.x = h4.x + gam * (v.x + p4.x + b4.x);
        x.y = h4.y + gam * (v.y + p4.y + b4.y);
        x.z = h4.z + gam * (v.z + p4.z + b4.z);
        x.w = h4.w + gam * (v.w + p4.w + b4.w);
        ((float4*)g_X)[(size_t)rowg * 256 + cc4] = x;
        float s2  = x.x + x.y + x.z + x.w;
        float ss2 = x.x * x.x + x.y * x.y + x.z * x.z + x.w * x.w;
        #pragma unroll
        for (int off = 4; off; off >>= 1) {
            s2  += __shfl_xor_sync(0xffffffffu, s2, off);
            ss2 += __shfl_xor_sync(0xffffffffu, ss2, off);
        }
        if ((tid & 7) == 0) g_part[rowg * 32 + bn] = make_float2(s2, ss2);
    }
}

// ---------------- LayerNorm: warp per row, normalize-only ----------------
__global__ void __launch_bounds__(256) ln_kernel(const float* __restrict__ lns,
                                                 const float* __restrict__ lnb,
                                                 float* __restrict__ out) {
    const int tid = threadIdx.x;
    const int lane = tid & 31;
    const int row = blockIdx.x * 8 + (tid >> 5);
    float2 p = g_part[row * 32 + lane];
    float s = p.x, ss = p.y;
    #pragma unroll
    for (int off = 16; off; off >>= 1) {
        s  += __shfl_xor_sync(0xffffffffu, s, off);
        ss += __shfl_xor_sync(0xffffffffu, ss, off);
    }
    const float mean = s * (1.f / 1024.f);
    const float inv  = rsqrtf(ss * (1.f / 1024.f) - mean * mean + LN_EPS);
    #pragma unroll
    for (int j = 0; j < 8; j++) {
        int c4 = lane + j * 32;
        float4 x = ((const float4*)g_X)[(size_t)row * 256 + c4];
        float4 sc = ((const float4*)lns)[c4];
        float4 bi = ((const float4*)lnb)[c4];
        float4 o;
        o.x = (x.x - mean) * inv * sc.x + bi.x;
        o.y = (x.y - mean) * inv * sc.y + bi.y;
        o.z = (x.z - mean) * inv * sc.z + bi.z;
        o.w = (x.w - mean) * inv * sc.w + bi.w;
        ((float4*)out)[(size_t)row * 256 + c4] = o;
    }
}

// ---------------- launch: kernel launches ONLY ----------------
extern "C" void kernel_launch(void* const* d_in, const int* in_sizes, int n_in,
                              void* d_out, int out_size) {
    const float* hA    = (const float*)d_in[0];
    const float* pool  = (const float*)d_in[1];
    const float* alpha = (const float*)d_in[2];
    const float* W     = (const float*)d_in[3];
    const float* bb    = (const float*)d_in[4];
    const float* gamma = (const float*)d_in[5];
    const float* lns   = (const float*)d_in[6];
    const float* lnb   = (const float*)d_in[7];
    float* out = (float*)d_out;

    k1_kernel<<<273, 256>>>(hA, W, pool, alpha);
    k2_kernel<<<256, 128>>>(hA, bb, gamma);
    ln_kernel<<<32, 256>>>(lns, lnb, out);
}